// round 13
// baseline (speedup 1.0000x reference)
#include <cuda_runtime.h>

#define BATCH 2
#define NCAM  6
#define CH    128
#define IH    16
#define IW    44
#define ND    64
#define HW    (IH*IW)                 // 704
#define NPTS  (NCAM*ND*IH*IW)         // 270336 geometry points (batch-independent)
#define BEV_H 256
#define BEV_W 256
#define NBIN  (BEV_H*BEV_W)           // 65536
#define NTILE (NBIN/32)               // 2048
#define CAMSTRIDE (NCAM*ND*HW)        // depth elements per batch
#define B1OFF  (NCAM*HW*CH)           // featT offset of batch 1

#define PT_BLOCKS   (NPTS/256)        // 1056
#define TR_BLOCKS   ((CH/32)*(HW/32)*BATCH*NCAM)  // 1056
#define FILL_BLOCKS (NPTS/1024)       // 264

typedef unsigned long long ull;

// Static scratch (allocation-free per harness rules)
__device__ float g_featT[(size_t)BATCH*NCAM*HW*CH];  // feat channel-last: (bn, hw, c)
__device__ int   g_bin[NPTS];                        // bin index or -1
__device__ __align__(16) int g_cnt_i[NBIN];          // per-bin count (re-zeroed each run)
__device__ __align__(16) int g_off[NBIN+1];          // CSR offsets (exclusive)
__device__ __align__(16) int g_wptr[NBIN];           // write cursors for fill
__device__ int   g_bsum[64];
__device__ volatile int g_flag[64];                  // scan publish flags (re-zeroed each run)
__device__ int   g_sched[NTILE];                     // tile schedule, hot first
__device__ __align__(16) float4 g_list[NPTS];        // {fpix*CH as int, pad, d0, d1}

// ---------------------------------------------------------------------------
// In-block camera setup (geometry identical across batch; b=0 slices).
// ---------------------------------------------------------------------------
__device__ __forceinline__ void cam_setup(const float* __restrict__ intr,
                                          const float* __restrict__ extr,
                                          const int* __restrict__ pimg_h,
                                          const int* __restrict__ pimg_w,
                                          float* sKi, float* sRm, float* stv) {
    int n = threadIdx.x;
    if (n < NCAM) {
        float img_h = (float)pimg_h[0], img_w = (float)pimg_w[0];
        float sx = (float)IW / (img_w / 16.0f);
        float sy = (float)IH / (img_h / 16.0f);
        float rs0 = 16.0f / sx, rs1 = 16.0f / sy, rs2 = 1.0f;

        const float* Kp = intr + n*9;
        float a = Kp[0]*rs0, b = Kp[1]*rs0, c = Kp[2]*rs0;
        float d = Kp[3]*rs1, e = Kp[4]*rs1, f = Kp[5]*rs1;
        float g = Kp[6]*rs2, h = Kp[7]*rs2, i = Kp[8]*rs2;
        float A  = e*i - f*h;
        float Bc = -(d*i - f*g);
        float Cc = d*h - e*g;
        float det = a*A + b*Bc + c*Cc;
        float id = 1.0f / det;
        float* Ki = sKi + n*9;
        Ki[0] = A*id;             Ki[1] = (c*h - b*i)*id;  Ki[2] = (b*f - c*e)*id;
        Ki[3] = Bc*id;            Ki[4] = (a*i - c*g)*id;  Ki[5] = (c*d - a*f)*id;
        Ki[6] = Cc*id;            Ki[7] = (b*g - a*h)*id;  Ki[8] = (a*e - b*d)*id;

        const float* Ep = extr + n*16;
        #pragma unroll
        for (int r = 0; r < 3; r++) {
            #pragma unroll
            for (int cc = 0; cc < 3; cc++) sRm[n*9 + r*3+cc] = Ep[r*4+cc];
            stv[n*3 + r] = Ep[r*4+3];
        }
    }
}

// ---------------------------------------------------------------------------
// Fused kernel A: blocks [0, PT_BLOCKS) -> point geometry (bin + count,
// warp-aggregated atomics); blocks [PT_BLOCKS, ...) -> feat transpose.
// ---------------------------------------------------------------------------
__global__ void __launch_bounds__(256) pointA_kernel(
        const float* __restrict__ feat,
        const float* __restrict__ intr, const float* __restrict__ extr,
        const int* __restrict__ pimg_h, const int* __restrict__ pimg_w) {
    if (blockIdx.x < PT_BLOCKS) {
        __shared__ float sKi[NCAM*9], sRm[NCAM*9], stv[NCAM*3];
        cam_setup(intr, extr, pimg_h, pimg_w, sKi, sRm, stv);
        __syncthreads();

        int wp = blockIdx.x * 256 + threadIdx.x;
        int lane = threadIdx.x & 31;
        int w   = wp % IW;  int t = wp / IW;
        int h   = t % IH;   t /= IH;
        int dci = t % ND;
        int n   = t / ND;

        float dd = 1.0f + (59.0f / 63.0f) * (float)dci;  // linspace(1,60,64)
        float ux = (float)w * dd;
        float vy = (float)h * dd;

        const float* Ki = sKi + n*9;
        float pcx = Ki[0]*ux + Ki[1]*vy + Ki[2]*dd;
        float pcy = Ki[3]*ux + Ki[4]*vy + Ki[5]*dd;
        float pcz = Ki[6]*ux + Ki[7]*vy + Ki[8]*dd;

        const float* Rm = sRm + n*9;
        const float* tv = stv + n*3;
        float px = Rm[0]*pcx + Rm[1]*pcy + Rm[2]*pcz + tv[0];
        float py = Rm[3]*pcx + Rm[4]*pcy + Rm[5]*pcz + tv[1];
        float pz = Rm[6]*pcx + Rm[7]*pcy + Rm[8]*pcz + tv[2];

        int xi = (int)__fdiv_rn(px - (-51.2f), 0.4f);
        int yi = (int)__fdiv_rn(py - (-51.2f), 0.4f);
        bool valid = (xi >= 0) & (xi < BEV_W) & (yi >= 0) & (yi < BEV_H)
                   & (pz >= -5.0f) & (pz <= 3.0f);

        int bin = valid ? (yi * BEV_W + xi) : -1;
        g_bin[wp] = bin;
        // warp-aggregated count atomics
        unsigned mask = __match_any_sync(0xffffffffu, bin);
        if (bin >= 0) {
            int leader = __ffs(mask) - 1;
            if (lane == leader) atomicAdd(&g_cnt_i[bin], __popc(mask));
        }
    } else {
        __shared__ float tile[32][33];
        int tb  = blockIdx.x - PT_BLOCKS;
        int c0  = (tb & 3) * 32;          // CH/32 = 4
        int hw0 = ((tb >> 2) % 22) * 32;  // HW/32 = 22
        int bn  = tb / 88;
        int x = threadIdx.x & 31, y = threadIdx.x >> 5;
        const float* src = feat + (size_t)bn * CH * HW;
        #pragma unroll
        for (int k = 0; k < 4; k++)
            tile[y + k*8][x] = src[(size_t)(c0 + y + k*8) * HW + hw0 + x];
        __syncthreads();
        #pragma unroll
        for (int k = 0; k < 4; k++)
            g_featT[((size_t)bn * HW + hw0 + y + k*8) * CH + c0 + x] = tile[x][y + k*8];
    }
}

// ---------------------------------------------------------------------------
// Single-kernel scan: 64 blocks x 256 threads x int4 (all co-resident).
// ---------------------------------------------------------------------------
__global__ void __launch_bounds__(256) scan_kernel() {
    __shared__ int wsum[8], wexcl[8], sexcl[64];
    int t   = threadIdx.x;
    int bid = blockIdx.x;
    int gb  = bid * 1024 + t * 4;
    int4 c = *(const int4*)&g_cnt_i[gb];
    int s = c.x + c.y + c.z + c.w;
    int lane = t & 31, wid = t >> 5;
    int incl = s;
    #pragma unroll
    for (int d = 1; d < 32; d <<= 1) {
        int v = __shfl_up_sync(0xffffffffu, incl, d);
        if (lane >= d) incl += v;
    }
    if (lane == 31) wsum[wid] = incl;
    __syncthreads();
    if (t < 8) {
        int v = wsum[t];
        int iv = v;
        #pragma unroll
        for (int d = 1; d < 8; d <<= 1) {
            int u = __shfl_up_sync(0xffu, iv, d);
            if (t >= d) iv += u;
        }
        wexcl[t] = iv - v;
    }
    __syncthreads();
    int excl = incl - s + wexcl[wid];
    if (t == 255) {
        g_bsum[bid] = excl + s;
        __threadfence();
        g_flag[bid] = 1;
    }

    if (t < 64) {
        while (g_flag[t] == 0) { }
    }
    __syncthreads();
    __threadfence();
    if (t < 64) {
        int v = g_bsum[t];
        int iv = v;
        int l = t & 31;
        #pragma unroll
        for (int d = 1; d < 32; d <<= 1) {
            int u = __shfl_up_sync(0xffffffffu, iv, d);
            if (l >= d) iv += u;
        }
        if (t == 31) wsum[0] = iv;
        __syncwarp();
        sexcl[t] = iv - v;
    }
    __syncthreads();
    int base = sexcl[bid] + ((bid >= 32) ? wsum[0] : 0);
    int4 o;
    o.x = base + excl; o.y = o.x + c.x; o.z = o.y + c.y; o.w = o.z + c.z;
    *(int4*)&g_off[gb]  = o;
    *(int4*)&g_wptr[gb] = o;
    if (bid == 63 && t == 255) g_off[NBIN] = o.w + c.w;
}

// ---------------------------------------------------------------------------
// Fused kernel B: fill fat list entries {fpix*CH, pad, d0, d1} with warp-
// aggregated cursor atomics; extra block builds the hot-first schedule and
// re-zeroes g_cnt_i / g_flag for replay (coalesced).
// ---------------------------------------------------------------------------
__global__ void __launch_bounds__(1024) fillB_kernel(const float* __restrict__ depth) {
    int t = threadIdx.x;
    if (blockIdx.x < FILL_BLOCKS) {
        int wp = blockIdx.x * 1024 + t;
        int bin = g_bin[wp];
        int lane = t & 31;

        unsigned mask = __match_any_sync(0xffffffffu, bin);
        if (bin >= 0) {
            int leader = __ffs(mask) - 1;
            int rank = __popc(mask & ((1u << lane) - 1u));
            int pos0 = 0;
            if (lane == leader) pos0 = atomicAdd(&g_wptr[bin], __popc(mask));
            pos0 = __shfl_sync(mask, pos0, leader);

            int w   = wp % IW;  int q = wp / IW;
            int h   = q % IH;   q /= IH;
            int dci = q % ND;
            int n   = q / ND;
            int hw  = h * IW + w;
            int dpo = (n * ND + dci) * HW + hw;

            float4 e;
            e.x = __int_as_float((n * HW + hw) * CH);
            e.y = 0.f;
            e.z = __ldg(&depth[dpo]);
            e.w = __ldg(&depth[CAMSTRIDE + dpo]);
            g_list[pos0 + rank] = e;
        }
    } else {
        // coalesced re-zero of counts + flags for next replay
        int4 z = {0, 0, 0, 0};
        #pragma unroll
        for (int j = 0; j < 16; j++)
            *(int4*)&g_cnt_i[(j * 1024 + t) * 4] = z;
        if (t < 64) *(int*)&g_flag[t] = 0;

        // hot-first schedule over 2048 tiles
        __shared__ int bcnt[8], bbase[8];
        if (t < 8) bcnt[t] = 0;
        __syncthreads();
        int ks[2];
        #pragma unroll
        for (int j = 0; j < 2; j++) {
            int tile = t + j * 1024;
            int cnt = g_off[tile*32 + 32] - g_off[tile*32];
            int k = cnt > 4096 ? 0 : cnt > 2048 ? 1 : cnt > 1024 ? 2 : cnt > 512 ? 3 :
                    cnt > 256  ? 4 : cnt > 128  ? 5 : cnt > 64   ? 6 : 7;
            ks[j] = k;
            atomicAdd(&bcnt[k], 1);
        }
        __syncthreads();
        if (t == 0) {
            int r = 0;
            #pragma unroll
            for (int k = 0; k < 8; k++) { bbase[k] = r; r += bcnt[k]; }
        }
        __syncthreads();
        #pragma unroll
        for (int j = 0; j < 2; j++) {
            int pos = atomicAdd(&bbase[ks[j]], 1);
            g_sched[pos] = t + j * 1024;
        }
    }
}

// ---------------------------------------------------------------------------
// FMA helper on packed f32x2 accumulators.
// ---------------------------------------------------------------------------
__device__ __forceinline__ void fma_point(int foff, float d0, float d1, int lane,
        ull& a0x, ull& a0y, ull& a1x, ull& a1y) {
    ull d0p, d1p;
    asm("mov.b64 %0, {%1, %1};" : "=l"(d0p) : "f"(d0));
    asm("mov.b64 %0, {%1, %1};" : "=l"(d1p) : "f"(d1));
    ulonglong2 v0 = *((const ulonglong2*)(g_featT + foff) + lane);
    ulonglong2 v1 = *((const ulonglong2*)(g_featT + (B1OFF + foff)) + lane);
    asm("fma.rn.f32x2 %0, %1, %2, %0;" : "+l"(a0x) : "l"(v0.x), "l"(d0p));
    asm("fma.rn.f32x2 %0, %1, %2, %0;" : "+l"(a0y) : "l"(v0.y), "l"(d0p));
    asm("fma.rn.f32x2 %0, %1, %2, %0;" : "+l"(a1x) : "l"(v1.x), "l"(d1p));
    asm("fma.rn.f32x2 %0, %1, %2, %0;" : "+l"(a1y) : "l"(v1.y), "l"(d1p));
}

// Generic run (phase 2): lane-parallel list prefetch + shuffle broadcast.
__device__ __forceinline__ void accum_run(int beg, int end, int lane,
        ull& a0x, ull& a0y, ull& a1x, ull& a1y) {
    for (int base = beg; base < end; base += 32) {
        int m = end - base;  if (m > 32) m = 32;
        float4 e = {0.f, 0.f, 0.f, 0.f};
        if (lane < m) e = g_list[base + lane];
        int fo = __float_as_int(e.x);

        #pragma unroll 4
        for (int j = 0; j < m; j++) {
            int   foff = __shfl_sync(0xffffffffu, fo,  j);
            float d0   = __shfl_sync(0xffffffffu, e.z, j);
            float d1   = __shfl_sync(0xffffffffu, e.w, j);
            fma_point(foff, d0, d1, lane, a0x, a0y, a1x, a1y);
        }
    }
}

__device__ __forceinline__ void unpack8(ull a0x, ull a0y, ull a1x, ull a1y,
        float& f0, float& f1, float& f2, float& f3,
        float& f4, float& f5, float& f6, float& f7) {
    asm("mov.b64 {%0, %1}, %2;" : "=f"(f0), "=f"(f1) : "l"(a0x));
    asm("mov.b64 {%0, %1}, %2;" : "=f"(f2), "=f"(f3) : "l"(a0y));
    asm("mov.b64 {%0, %1}, %2;" : "=f"(f4), "=f"(f5) : "l"(a1x));
    asm("mov.b64 {%0, %1}, %2;" : "=f"(f6), "=f"(f7) : "l"(a1y));
}

// ---------------------------------------------------------------------------
// Gather: block = 32-bin tile (hot-first), 8 warps, warp owns 4 bins.
// Accumulators are PRE-SCALED by 1/(cnt+1e-5) before hitting smem, so the
// epilogue is a bare LDS+STG. Phase-1 smem writes are conflict-free STS.128
// (pad 132 -> float4 row stride 33, lane-consecutive). Rolling 2-deep list
// preload keeps registers in check while overlapping bin k+1's list load
// with bin k's processing. Phase 2: packed-queue chunk stealing, atomic
// smem flush (pre-scaled).
// ---------------------------------------------------------------------------
#define CAP    32
#define CHUNK  64
#define MAXQ   512
#define ACCW   132   // CH + 4: float4 row stride 33 (odd) -> conflict-free STS.128
__global__ void __launch_bounds__(256, 5) gather_kernel(float* __restrict__ out) {
    __shared__ float acc[BATCH][32][ACCW];   // 33.8 KB
    __shared__ float sinv[32];
    __shared__ int   cq[MAXQ];               // bl<<26 | len<<19 | beg
    __shared__ int   sQn, sCtr;

    int tile = g_sched[blockIdx.x];
    int bin0 = tile * 32;
    int tid  = threadIdx.x;
    int warp = tid >> 5;
    int lane = tid & 31;

    if (tid == 0) { sQn = 0; sCtr = 0; }
    __syncthreads();

    // ---- Phase 1: offsets for all 4 owned bins, rolling 2-deep preload ----
    int begA[4], cntA[4];
    #pragma unroll
    for (int k = 0; k < 4; k++) {
        int bin = bin0 + warp + k * 8;
        begA[k] = g_off[bin];
        cntA[k] = g_off[bin + 1] - begA[k];
    }

    float4 ecur = {0.f, 0.f, 0.f, 0.f};
    {
        int m = cntA[0] < CAP ? cntA[0] : CAP;
        if (lane < m) ecur = g_list[begA[0] + lane];
    }

    #pragma unroll
    for (int k = 0; k < 4; k++) {
        // preload next bin's entries while processing this one
        float4 enext = {0.f, 0.f, 0.f, 0.f};
        if (k < 3) {
            int mn = cntA[k+1] < CAP ? cntA[k+1] : CAP;
            if (lane < mn) enext = g_list[begA[k+1] + lane];
        }

        int bl  = warp + k * 8;
        int cnt = cntA[k];
        int m   = cnt < CAP ? cnt : CAP;
        float inv = __fdiv_rn(1.0f, (float)cnt + 1e-5f);
        if (lane == 0) sinv[bl] = inv;
        int fo = __float_as_int(ecur.x);

        ull a0x = 0, a0y = 0, a1x = 0, a1y = 0;
        #pragma unroll 4
        for (int j = 0; j < m; j++) {
            int   foff = __shfl_sync(0xffffffffu, fo,     j);
            float d0   = __shfl_sync(0xffffffffu, ecur.z, j);
            float d1   = __shfl_sync(0xffffffffu, ecur.w, j);
            fma_point(foff, d0, d1, lane, a0x, a0y, a1x, a1y);
        }

        float f0, f1, f2, f3, f4, f5, f6, f7;
        unpack8(a0x, a0y, a1x, a1y, f0, f1, f2, f3, f4, f5, f6, f7);
        // pre-scaled, conflict-free STS.128 (float4 idx = 33*bl + lane)
        ((float4*)&acc[0][bl][0])[lane] = make_float4(f0*inv, f1*inv, f2*inv, f3*inv);
        ((float4*)&acc[1][bl][0])[lane] = make_float4(f4*inv, f5*inv, f6*inv, f7*inv);

        if (cnt > CAP && lane == 0) {
            int rem = cnt - CAP;
            int nch = (rem + CHUNK - 1) / CHUNK;
            if (nch > 15) nch = 15;
            int cl = (rem + nch - 1) / nch;
            int qb = atomicAdd(&sQn, nch);
            int b0 = begA[k] + CAP;
            for (int j = 0; j < nch; j++) {
                int l = rem - j * cl; if (l > cl) l = cl;
                cq[qb + j] = (bl << 26) | (l << 19) | (b0 + j * cl);
            }
        }
        ecur = enext;
    }
    __syncthreads();

    // ---- Phase 2: steal remainder chunks of hot bins (pre-scaled flush) ----
    int total = sQn;
    while (true) {
        int cidx;
        if (lane == 0) cidx = atomicAdd(&sCtr, 1);
        cidx = __shfl_sync(0xffffffffu, cidx, 0);
        if (cidx >= total) break;

        int e   = cq[cidx];
        int bl  = e >> 26;
        int len = (e >> 19) & 0x7F;
        int beg = e & 0x7FFFF;
        ull a0x = 0, a0y = 0, a1x = 0, a1y = 0;
        accum_run(beg, beg + len, lane, a0x, a0y, a1x, a1y);

        float inv = sinv[bl];
        float f0, f1, f2, f3, f4, f5, f6, f7;
        unpack8(a0x, a0y, a1x, a1y, f0, f1, f2, f3, f4, f5, f6, f7);
        int c4 = lane * 4;
        atomicAdd(&acc[0][bl][c4+0], f0*inv);  atomicAdd(&acc[0][bl][c4+1], f1*inv);
        atomicAdd(&acc[0][bl][c4+2], f2*inv);  atomicAdd(&acc[0][bl][c4+3], f3*inv);
        atomicAdd(&acc[1][bl][c4+0], f4*inv);  atomicAdd(&acc[1][bl][c4+1], f5*inv);
        atomicAdd(&acc[1][bl][c4+2], f6*inv);  atomicAdd(&acc[1][bl][c4+3], f7*inv);
    }
    __syncthreads();

    // ---- Epilogue: bare LDS+STG, 256 rows (b,c), coalesced 128B stores ----
    #pragma unroll
    for (int r = warp; r < BATCH * CH; r += 8) {
        int b = r >> 7;
        int c = r & 127;
        out[((size_t)(b * CH + c)) * NBIN + bin0 + lane] = acc[b][lane][c];
    }
}

extern "C" void kernel_launch(void* const* d_in, const int* in_sizes, int n_in,
                              void* d_out, int out_size) {
    const float* feat  = (const float*)d_in[0];
    const float* depth = (const float*)d_in[1];
    const float* intr  = (const float*)d_in[2];
    const float* extr  = (const float*)d_in[3];
    const int*   img_h = (const int*)d_in[4];
    const int*   img_w = (const int*)d_in[5];
    float* out = (float*)d_out;

    pointA_kernel<<<PT_BLOCKS + TR_BLOCKS, 256>>>(feat, intr, extr, img_h, img_w);
    scan_kernel<<<64, 256>>>();
    fillB_kernel<<<FILL_BLOCKS + 1, 1024>>>(depth);
    gather_kernel<<<NTILE, 256>>>(out);
}

// round 14
// speedup vs baseline: 1.0450x; 1.0450x over previous
#include <cuda_runtime.h>

#define BATCH 2
#define NCAM  6
#define CH    128
#define IH    16
#define IW    44
#define ND    64
#define HW    (IH*IW)                 // 704
#define NPTS  (NCAM*ND*IH*IW)         // 270336
#define BEV_H 256
#define BEV_W 256
#define NBIN  (BEV_H*BEV_W)           // 65536
#define NTILE (NBIN/32)               // 2048
#define CAMSTRIDE (NCAM*ND*HW)
#define B1OFF  (NCAM*HW*CH)

#define GRID   592                    // 148 SMs x 4 blocks, co-resident
#define GEO_UNITS  (NPTS/256)         // 1056
#define TR_UNITS   ((CH/32)*(HW/32)*BATCH*NCAM)  // 1056
#define A_UNITS    (GEO_UNITS + TR_UNITS)
#define FILL_UNITS (NPTS/256)         // 1056
#define C_UNITS    (FILL_UNITS + 16 + 1 + 1)     // fill + cnt-zero + flag/ctr-zero + sched

#define CAP    32
#define CHUNK  64
#define MAXQ   512
#define ACCW   132

typedef unsigned long long ull;

// Static scratch (allocation-free per harness rules)
__device__ float g_featT[(size_t)BATCH*NCAM*HW*CH];
__device__ int   g_bin[NPTS];
__device__ __align__(16) int g_cnt_i[NBIN];          // re-zeroed each run (phase C)
__device__ __align__(16) int g_off[NBIN+1];
__device__ __align__(16) int g_wptr[NBIN];
__device__ int   g_bsum[64];
__device__ volatile int g_flag[64];                  // scan flags (re-zeroed phase C)
__device__ int   g_sched[NTILE];
__device__ __align__(16) float4 g_list[NPTS];
__device__ int   g_tctr;                             // gather tile claim ctr (reset phase C)
__device__ int          g_barCnt[3];                 // grid barrier ring
__device__ volatile int g_barRel[3];

// ---------------------------------------------------------------------------
// Grid-wide barrier ring (3 barriers used in order 0,1,2 per kernel run).
// Releaser of barrier k: resets cnt[k], pre-resets rel[(k+1)%3] (provably not
// in use: guarded by this barrier within the run / kernel boundary across
// runs), then sets rel[k]. Zero-init state is valid for the first run.
// ---------------------------------------------------------------------------
__device__ __forceinline__ void grid_barrier(int k) {
    __syncthreads();
    if (threadIdx.x == 0) {
        __threadfence();
        int ret = atomicAdd(&g_barCnt[k], 1);
        if (ret == GRID - 1) {
            g_barCnt[k] = 0;
            g_barRel[(k + 1) % 3] = 0;
            __threadfence();
            g_barRel[k] = 1;
        } else {
            while (g_barRel[k] == 0) { }
            __threadfence();
        }
    }
    __syncthreads();
}

// ---------------------------------------------------------------------------
// FMA helpers on packed f32x2 accumulators.
// ---------------------------------------------------------------------------
__device__ __forceinline__ void fma_point(int foff, float d0, float d1, int lane,
        ull& a0x, ull& a0y, ull& a1x, ull& a1y) {
    ull d0p, d1p;
    asm("mov.b64 %0, {%1, %1};" : "=l"(d0p) : "f"(d0));
    asm("mov.b64 %0, {%1, %1};" : "=l"(d1p) : "f"(d1));
    ulonglong2 v0 = *((const ulonglong2*)(g_featT + foff) + lane);
    ulonglong2 v1 = *((const ulonglong2*)(g_featT + (B1OFF + foff)) + lane);
    asm("fma.rn.f32x2 %0, %1, %2, %0;" : "+l"(a0x) : "l"(v0.x), "l"(d0p));
    asm("fma.rn.f32x2 %0, %1, %2, %0;" : "+l"(a0y) : "l"(v0.y), "l"(d0p));
    asm("fma.rn.f32x2 %0, %1, %2, %0;" : "+l"(a1x) : "l"(v1.x), "l"(d1p));
    asm("fma.rn.f32x2 %0, %1, %2, %0;" : "+l"(a1y) : "l"(v1.y), "l"(d1p));
}

__device__ __forceinline__ void accum_run(int beg, int end, int lane,
        ull& a0x, ull& a0y, ull& a1x, ull& a1y) {
    for (int base = beg; base < end; base += 32) {
        int m = end - base;  if (m > 32) m = 32;
        float4 e = {0.f, 0.f, 0.f, 0.f};
        if (lane < m) e = g_list[base + lane];
        int fo = __float_as_int(e.x);
        #pragma unroll 4
        for (int j = 0; j < m; j++) {
            int   foff = __shfl_sync(0xffffffffu, fo,  j);
            float d0   = __shfl_sync(0xffffffffu, e.z, j);
            float d1   = __shfl_sync(0xffffffffu, e.w, j);
            fma_point(foff, d0, d1, lane, a0x, a0y, a1x, a1y);
        }
    }
}

__device__ __forceinline__ void unpack8(ull a0x, ull a0y, ull a1x, ull a1y,
        float& f0, float& f1, float& f2, float& f3,
        float& f4, float& f5, float& f6, float& f7) {
    asm("mov.b64 {%0, %1}, %2;" : "=f"(f0), "=f"(f1) : "l"(a0x));
    asm("mov.b64 {%0, %1}, %2;" : "=f"(f2), "=f"(f3) : "l"(a0y));
    asm("mov.b64 {%0, %1}, %2;" : "=f"(f4), "=f"(f5) : "l"(a1x));
    asm("mov.b64 {%0, %1}, %2;" : "=f"(f6), "=f"(f7) : "l"(a1y));
}

// ---------------------------------------------------------------------------
// Persistent mega-kernel: all phases, one launch.
// ---------------------------------------------------------------------------
__global__ void __launch_bounds__(256, 4) mega_kernel(
        const float* __restrict__ feat,  const float* __restrict__ depth,
        const float* __restrict__ intr,  const float* __restrict__ extr,
        const int* __restrict__ pimg_h,  const int* __restrict__ pimg_w,
        float* __restrict__ out) {
    __shared__ float s_acc[BATCH][32][ACCW];   // gather accumulators (aliased below)
    __shared__ float s_sinv[32];
    __shared__ int   s_cq[MAXQ];
    __shared__ int   s_misc[4];                // [0]=sQn [1]=sCtr [2]=claimed tile

    int bid  = blockIdx.x;
    int tid  = threadIdx.x;
    int warp = tid >> 5;
    int lane = tid & 31;
    float* s_accf = &s_acc[0][0][0];

    // ===================== Phase A: camera setup + geometry + transpose =====
    {
        // camera constants live above the transpose tile scratch region
        float* sKi = s_accf + 2000;
        float* sRm = sKi + NCAM*9;
        float* stv = sRm + NCAM*9;
        if (tid < NCAM) {
            int n = tid;
            float img_h = (float)pimg_h[0], img_w = (float)pimg_w[0];
            float sx = (float)IW / (img_w / 16.0f);
            float sy = (float)IH / (img_h / 16.0f);
            float rs0 = 16.0f / sx, rs1 = 16.0f / sy, rs2 = 1.0f;
            const float* Kp = intr + n*9;
            float a = Kp[0]*rs0, b = Kp[1]*rs0, c = Kp[2]*rs0;
            float d = Kp[3]*rs1, e = Kp[4]*rs1, f = Kp[5]*rs1;
            float g = Kp[6]*rs2, h = Kp[7]*rs2, i = Kp[8]*rs2;
            float A  = e*i - f*h;
            float Bc = -(d*i - f*g);
            float Cc = d*h - e*g;
            float det = a*A + b*Bc + c*Cc;
            float id = 1.0f / det;
            float* Ki = sKi + n*9;
            Ki[0] = A*id;   Ki[1] = (c*h - b*i)*id;  Ki[2] = (b*f - c*e)*id;
            Ki[3] = Bc*id;  Ki[4] = (a*i - c*g)*id;  Ki[5] = (c*d - a*f)*id;
            Ki[6] = Cc*id;  Ki[7] = (b*g - a*h)*id;  Ki[8] = (a*e - b*d)*id;
            const float* Ep = extr + n*16;
            #pragma unroll
            for (int r = 0; r < 3; r++) {
                #pragma unroll
                for (int cc = 0; cc < 3; cc++) sRm[n*9 + r*3+cc] = Ep[r*4+cc];
                stv[n*3 + r] = Ep[r*4+3];
            }
        }
        __syncthreads();

        float (*tile)[33] = (float(*)[33])s_accf;   // floats [0, 1056)
        for (int u = bid; u < A_UNITS; u += GRID) {
            if (u < GEO_UNITS) {
                int wp = u * 256 + tid;
                int w   = wp % IW;  int t = wp / IW;
                int h   = t % IH;   t /= IH;
                int dci = t % ND;
                int n   = t / ND;

                float dd = 1.0f + (59.0f / 63.0f) * (float)dci;
                float ux = (float)w * dd;
                float vy = (float)h * dd;

                const float* Ki = sKi + n*9;
                float pcx = Ki[0]*ux + Ki[1]*vy + Ki[2]*dd;
                float pcy = Ki[3]*ux + Ki[4]*vy + Ki[5]*dd;
                float pcz = Ki[6]*ux + Ki[7]*vy + Ki[8]*dd;

                const float* Rm = sRm + n*9;
                const float* tv = stv + n*3;
                float px = Rm[0]*pcx + Rm[1]*pcy + Rm[2]*pcz + tv[0];
                float py = Rm[3]*pcx + Rm[4]*pcy + Rm[5]*pcz + tv[1];
                float pz = Rm[6]*pcx + Rm[7]*pcy + Rm[8]*pcz + tv[2];

                int xi = (int)__fdiv_rn(px - (-51.2f), 0.4f);
                int yi = (int)__fdiv_rn(py - (-51.2f), 0.4f);
                bool valid = (xi >= 0) & (xi < BEV_W) & (yi >= 0) & (yi < BEV_H)
                           & (pz >= -5.0f) & (pz <= 3.0f);
                int bin = valid ? (yi * BEV_W + xi) : -1;
                g_bin[wp] = bin;
                unsigned mask = __match_any_sync(0xffffffffu, bin);
                if (bin >= 0) {
                    int leader = __ffs(mask) - 1;
                    if (lane == leader) atomicAdd(&g_cnt_i[bin], __popc(mask));
                }
            } else {
                int tb  = u - GEO_UNITS;
                int c0  = (tb & 3) * 32;
                int hw0 = ((tb >> 2) % 22) * 32;
                int bn  = tb / 88;
                int x = lane, y = warp;
                const float* src = feat + (size_t)bn * CH * HW;
                #pragma unroll
                for (int k = 0; k < 4; k++)
                    tile[y + k*8][x] = src[(size_t)(c0 + y + k*8) * HW + hw0 + x];
                __syncthreads();
                #pragma unroll
                for (int k = 0; k < 4; k++)
                    g_featT[((size_t)bn * HW + hw0 + y + k*8) * CH + c0 + x] = tile[x][y + k*8];
            }
            __syncthreads();
        }
    }
    grid_barrier(0);

    // ===================== Phase B: scan (blocks 0..63) =====================
    if (bid < 64) {
        int* wsum  = s_cq + 0;
        int* wexcl = s_cq + 8;
        int* sexcl = s_cq + 16;
        int gb = bid * 1024 + tid * 4;
        int4 c = *(const int4*)&g_cnt_i[gb];
        int s = c.x + c.y + c.z + c.w;
        int incl = s;
        #pragma unroll
        for (int d = 1; d < 32; d <<= 1) {
            int v = __shfl_up_sync(0xffffffffu, incl, d);
            if (lane >= d) incl += v;
        }
        if (lane == 31) wsum[warp] = incl;
        __syncthreads();
        if (tid < 8) {
            int v = wsum[tid];
            int iv = v;
            #pragma unroll
            for (int d = 1; d < 8; d <<= 1) {
                int u = __shfl_up_sync(0xffu, iv, d);
                if (tid >= d) iv += u;
            }
            wexcl[tid] = iv - v;
        }
        __syncthreads();
        int excl = incl - s + wexcl[warp];
        if (tid == 255) {
            g_bsum[bid] = excl + s;
            __threadfence();
            g_flag[bid] = 1;
        }
        if (tid < 64) {
            while (g_flag[tid] == 0) { }
        }
        __syncthreads();
        __threadfence();
        if (tid < 64) {
            int v = g_bsum[tid];
            int iv = v;
            #pragma unroll
            for (int d = 1; d < 32; d <<= 1) {
                int u = __shfl_up_sync(0xffffffffu, iv, d);
                if (lane >= d) iv += u;
            }
            if (tid == 31) wsum[0] = iv;
            __syncwarp();
            sexcl[tid] = iv - v;
        }
        __syncthreads();
        int base = sexcl[bid] + ((bid >= 32) ? wsum[0] : 0);
        int4 o;
        o.x = base + excl; o.y = o.x + c.x; o.z = o.y + c.y; o.w = o.z + c.z;
        *(int4*)&g_off[gb]  = o;
        *(int4*)&g_wptr[gb] = o;
        if (bid == 63 && tid == 255) g_off[NBIN] = o.w + c.w;
    }
    grid_barrier(1);

    // ===================== Phase C: fill + zeroing + schedule ===============
    for (int u = bid; u < C_UNITS; u += GRID) {
        if (u < FILL_UNITS) {
            int wp = u * 256 + tid;
            int bin = g_bin[wp];
            unsigned mask = __match_any_sync(0xffffffffu, bin);
            if (bin >= 0) {
                int leader = __ffs(mask) - 1;
                int rank = __popc(mask & ((1u << lane) - 1u));
                int pos0 = 0;
                if (lane == leader) pos0 = atomicAdd(&g_wptr[bin], __popc(mask));
                pos0 = __shfl_sync(mask, pos0, leader);

                int w   = wp % IW;  int q = wp / IW;
                int h   = q % IH;   q /= IH;
                int dci = q % ND;
                int n   = q / ND;
                int hw  = h * IW + w;
                int dpo = (n * ND + dci) * HW + hw;

                float4 e;
                e.x = __int_as_float((n * HW + hw) * CH);
                e.y = 0.f;
                e.z = __ldg(&depth[dpo]);
                e.w = __ldg(&depth[CAMSTRIDE + dpo]);
                g_list[pos0 + rank] = e;
            }
        } else if (u < FILL_UNITS + 16) {
            int cb = (u - FILL_UNITS) * 4096 + tid * 16;     // 16 ints per thread
            int4 z = {0, 0, 0, 0};
            #pragma unroll
            for (int j = 0; j < 4; j++)
                *(int4*)&g_cnt_i[cb + j * 4] = z;
        } else if (u < FILL_UNITS + 17) {
            if (tid < 64) *(int*)&g_flag[tid] = 0;
            if (tid == 64) g_tctr = 0;
        } else {
            // hot-first schedule over 2048 tiles (256 threads, 8 tiles each)
            int* bcnt  = s_cq + 0;
            int* bbase = s_cq + 8;
            if (tid < 8) bcnt[tid] = 0;
            __syncthreads();
            int ks[8];
            #pragma unroll
            for (int j = 0; j < 8; j++) {
                int tl = tid + j * 256;
                int cnt = g_off[tl*32 + 32] - g_off[tl*32];
                int k = cnt > 4096 ? 0 : cnt > 2048 ? 1 : cnt > 1024 ? 2 : cnt > 512 ? 3 :
                        cnt > 256  ? 4 : cnt > 128  ? 5 : cnt > 64   ? 6 : 7;
                ks[j] = k;
                atomicAdd(&bcnt[k], 1);
            }
            __syncthreads();
            if (tid == 0) {
                int r = 0;
                #pragma unroll
                for (int k = 0; k < 8; k++) { bbase[k] = r; r += bcnt[k]; }
            }
            __syncthreads();
            #pragma unroll
            for (int j = 0; j < 8; j++) {
                int pos = atomicAdd(&bbase[ks[j]], 1);
                g_sched[pos] = tid + j * 256;
            }
            __syncthreads();
        }
    }
    grid_barrier(2);

    // ===================== Phase D: gather, dynamic tile claiming ===========
    while (true) {
        if (tid == 0) {
            s_misc[2] = atomicAdd(&g_tctr, 1);
            s_misc[0] = 0;  s_misc[1] = 0;
        }
        __syncthreads();
        int tidx = s_misc[2];
        if (tidx >= NTILE) break;
        int bin0 = g_sched[tidx] * 32;

        // ---- Phase 1: 4 owned bins, rolling 2-deep list preload ----
        int begA[4], cntA[4];
        #pragma unroll
        for (int k = 0; k < 4; k++) {
            int bin = bin0 + warp + k * 8;
            begA[k] = g_off[bin];
            cntA[k] = g_off[bin + 1] - begA[k];
        }
        float4 ecur = {0.f, 0.f, 0.f, 0.f};
        {
            int m = cntA[0] < CAP ? cntA[0] : CAP;
            if (lane < m) ecur = g_list[begA[0] + lane];
        }
        #pragma unroll
        for (int k = 0; k < 4; k++) {
            float4 enext = {0.f, 0.f, 0.f, 0.f};
            if (k < 3) {
                int mn = cntA[k+1] < CAP ? cntA[k+1] : CAP;
                if (lane < mn) enext = g_list[begA[k+1] + lane];
            }
            int bl  = warp + k * 8;
            int cnt = cntA[k];
            int m   = cnt < CAP ? cnt : CAP;
            float inv = __fdiv_rn(1.0f, (float)cnt + 1e-5f);
            if (lane == 0) s_sinv[bl] = inv;
            int fo = __float_as_int(ecur.x);

            ull a0x = 0, a0y = 0, a1x = 0, a1y = 0;
            #pragma unroll 4
            for (int j = 0; j < m; j++) {
                int   foff = __shfl_sync(0xffffffffu, fo,     j);
                float d0   = __shfl_sync(0xffffffffu, ecur.z, j);
                float d1   = __shfl_sync(0xffffffffu, ecur.w, j);
                fma_point(foff, d0, d1, lane, a0x, a0y, a1x, a1y);
            }
            float f0, f1, f2, f3, f4, f5, f6, f7;
            unpack8(a0x, a0y, a1x, a1y, f0, f1, f2, f3, f4, f5, f6, f7);
            ((float4*)&s_acc[0][bl][0])[lane] = make_float4(f0*inv, f1*inv, f2*inv, f3*inv);
            ((float4*)&s_acc[1][bl][0])[lane] = make_float4(f4*inv, f5*inv, f6*inv, f7*inv);

            if (cnt > CAP && lane == 0) {
                int rem = cnt - CAP;
                int nch = (rem + CHUNK - 1) / CHUNK;
                if (nch > 15) nch = 15;
                int cl = (rem + nch - 1) / nch;
                int qb = atomicAdd(&s_misc[0], nch);
                int b0 = begA[k] + CAP;
                for (int j = 0; j < nch; j++) {
                    int l = rem - j * cl; if (l > cl) l = cl;
                    s_cq[qb + j] = (bl << 26) | (l << 19) | (b0 + j * cl);
                }
            }
            ecur = enext;
        }
        __syncthreads();

        // ---- Phase 2: steal remainder chunks of hot bins ----
        int total = s_misc[0];
        while (true) {
            int cidx;
            if (lane == 0) cidx = atomicAdd(&s_misc[1], 1);
            cidx = __shfl_sync(0xffffffffu, cidx, 0);
            if (cidx >= total) break;
            int e   = s_cq[cidx];
            int bl  = e >> 26;
            int len = (e >> 19) & 0x7F;
            int beg = e & 0x7FFFF;
            ull a0x = 0, a0y = 0, a1x = 0, a1y = 0;
            accum_run(beg, beg + len, lane, a0x, a0y, a1x, a1y);
            float inv = s_sinv[bl];
            float f0, f1, f2, f3, f4, f5, f6, f7;
            unpack8(a0x, a0y, a1x, a1y, f0, f1, f2, f3, f4, f5, f6, f7);
            int c4 = lane * 4;
            atomicAdd(&s_acc[0][bl][c4+0], f0*inv);  atomicAdd(&s_acc[0][bl][c4+1], f1*inv);
            atomicAdd(&s_acc[0][bl][c4+2], f2*inv);  atomicAdd(&s_acc[0][bl][c4+3], f3*inv);
            atomicAdd(&s_acc[1][bl][c4+0], f4*inv);  atomicAdd(&s_acc[1][bl][c4+1], f5*inv);
            atomicAdd(&s_acc[1][bl][c4+2], f6*inv);  atomicAdd(&s_acc[1][bl][c4+3], f7*inv);
        }
        __syncthreads();

        // ---- Epilogue: 256 rows (b,c), coalesced 128B stores ----
        #pragma unroll
        for (int r = warp; r < BATCH * CH; r += 8) {
            int b = r >> 7;
            int c = r & 127;
            out[((size_t)(b * CH + c)) * NBIN + bin0 + lane] = s_acc[b][lane][c];
        }
        __syncthreads();   // protect acc/s_misc before next tile
    }
}

extern "C" void kernel_launch(void* const* d_in, const int* in_sizes, int n_in,
                              void* d_out, int out_size) {
    const float* feat  = (const float*)d_in[0];
    const float* depth = (const float*)d_in[1];
    const float* intr  = (const float*)d_in[2];
    const float* extr  = (const float*)d_in[3];
    const int*   img_h = (const int*)d_in[4];
    const int*   img_w = (const int*)d_in[5];
    float* out = (float*)d_out;

    mega_kernel<<<GRID, 256>>>(feat, depth, intr, extr, img_h, img_w, out);
}